// round 1
// baseline (speedup 1.0000x reference)
#include <cuda_runtime.h>
#include <cstdint>

// ---------------------------------------------------------------------------
// DeformConv2d (B=8, C=64, H=W=64, GROUPS=4, 3x3, pad 1, stride 1)
//
// Kernel 1: grouped offset conv 64 -> 1728 (groups=4), writes g_off scratch.
// Kernel 2: group-softmax mask + bilinear sample + grouped main conv + bias.
// ---------------------------------------------------------------------------

#define B_      8
#define C_      64
#define H_      64
#define W_      64
#define G_      4
#define CG_     16          // C / G
#define KH_     3
#define KW_     3
#define K_      9
#define COFF_   1728        // C * K * 3
#define COFF_G  432         // per-group out channels of offset conv
#define HW_     4096        // H*W
#define KKN     144         // CG_ * K_

// 226 MB scratch for the offset-conv output, layout [B][1728][H][W]
__device__ float g_off[(size_t)B_ * COFF_ * HW_];

// ---------------------------------------------------------------------------
// Kernel 1: offset conv.
// CTA tile: 48 out-channels x 256 pixels (16x16). smem im2col sCol[144][256]
// plus weights sW[144][48]. Each thread: 6 oc x 8 px accumulators.
// ---------------------------------------------------------------------------
#define OCT 48
#define PXT 256

__global__ __launch_bounds__(256) void off_conv_kernel(
    const float* __restrict__ in,      // [B][C][H][W]
    const float* __restrict__ w_off,   // [1728][16][3][3]
    const float* __restrict__ b_off)   // [1728]
{
    extern __shared__ float smem[];
    float* sCol = smem;               // [144][256]
    float* sW   = smem + KKN * PXT;   // [144][48]

    const int b   = blockIdx.z;
    const int oc0 = blockIdx.y * OCT;             // 36 tiles, 48 | 432 so no group straddle
    const int g   = oc0 / COFF_G;                 // conv group -> input channels g*16..g*16+15
    const int h0  = (blockIdx.x >> 2) * 16;
    const int w0  = (blockIdx.x & 3) * 16;
    const int tid = threadIdx.x;

    // load weights: w_off[oc][kk] -> sW[kk][oc_local]
    for (int i = tid; i < OCT * KKN; i += 256) {
        int ocl = i / KKN;
        int kk  = i % KKN;
        sW[kk * OCT + ocl] = w_off[(oc0 + ocl) * KKN + kk];
    }

    // build im2col: sCol[kk][px], px = pr*16 + pc over the 16x16 pixel tile
    const float* inb = in + ((size_t)b * C_ + g * CG_) * HW_;
    for (int i = tid; i < KKN * PXT; i += 256) {
        int kk = i / PXT;
        int px = i % PXT;
        int cg = kk / K_;
        int t  = kk % K_;
        int ky = t / 3, kx = t % 3;
        int ih = h0 + (px >> 4) - 1 + ky;
        int iw = w0 + (px & 15) - 1 + kx;
        float v = 0.0f;
        if ((unsigned)ih < (unsigned)H_ && (unsigned)iw < (unsigned)W_)
            v = __ldg(inb + cg * HW_ + ih * W_ + iw);
        sCol[kk * PXT + px] = v;
    }
    __syncthreads();

    const int oc_s = tid >> 5;   // 0..7  -> oc base oc_s*6
    const int px_s = tid & 31;   // 0..31 -> px base px_s*8 (8 consecutive px)

    float acc[6][8];
#pragma unroll
    for (int j = 0; j < 6; ++j)
#pragma unroll
        for (int p = 0; p < 8; ++p) acc[j][p] = 0.0f;

    const float4* colBase = (const float4*)sCol;

#pragma unroll 4
    for (int kk = 0; kk < KKN; ++kk) {
        float4 a0 = colBase[kk * (PXT / 4) + px_s * 2];
        float4 a1 = colBase[kk * (PXT / 4) + px_s * 2 + 1];
        float wv[6];
#pragma unroll
        for (int j = 0; j < 6; ++j) wv[j] = sW[kk * OCT + oc_s * 6 + j];
#pragma unroll
        for (int j = 0; j < 6; ++j) {
            acc[j][0] = fmaf(wv[j], a0.x, acc[j][0]);
            acc[j][1] = fmaf(wv[j], a0.y, acc[j][1]);
            acc[j][2] = fmaf(wv[j], a0.z, acc[j][2]);
            acc[j][3] = fmaf(wv[j], a0.w, acc[j][3]);
            acc[j][4] = fmaf(wv[j], a1.x, acc[j][4]);
            acc[j][5] = fmaf(wv[j], a1.y, acc[j][5]);
            acc[j][6] = fmaf(wv[j], a1.z, acc[j][6]);
            acc[j][7] = fmaf(wv[j], a1.w, acc[j][7]);
        }
    }

    // store: 8 consecutive w positions per thread -> two float4 stores per oc
    const int px0 = px_s * 8;
    const int pr  = px0 >> 4;         // same row for all 8 px (8 | 16)
    const int pc0 = px0 & 15;         // 0 or 8
#pragma unroll
    for (int j = 0; j < 6; ++j) {
        int oc = oc0 + oc_s * 6 + j;
        float bv = __ldg(b_off + oc);
        float* dst = g_off + (size_t)(b * COFF_ + oc) * HW_ + (h0 + pr) * W_ + (w0 + pc0);
        float4 v0 = make_float4(acc[j][0] + bv, acc[j][1] + bv, acc[j][2] + bv, acc[j][3] + bv);
        float4 v1 = make_float4(acc[j][4] + bv, acc[j][5] + bv, acc[j][6] + bv, acc[j][7] + bv);
        ((float4*)dst)[0] = v0;
        ((float4*)dst)[1] = v1;
    }
}

// ---------------------------------------------------------------------------
// Kernel 2: per output pixel — read 12 offset values per (cg,k), softmax over
// groups, bilinear sample 4 group channels, accumulate grouped 3x3 conv into
// 64 register accumulators, add bias, store.
// ---------------------------------------------------------------------------
__global__ __launch_bounds__(128) void deform_main_kernel(
    const float* __restrict__ in,      // [B][C][H][W]
    const float* __restrict__ wmain,   // [64][16][3][3]
    const float* __restrict__ bias)    // [64]
{
    __shared__ float sW[G_ * CG_ * K_ * 16];   // [g][cg][k][ol]

    for (int i = threadIdx.x; i < 64 * KKN; i += 128) {
        int o  = i / KKN;
        int r  = i % KKN;
        int gq = o >> 4, ol = o & 15;
        int cg = r / K_, k = r % K_;
        sW[((gq * CG_ + cg) * K_ + k) * 16 + ol] = wmain[o * KKN + r];
    }
    __syncthreads();

    const int p = blockIdx.x * 128 + threadIdx.x;  // 0..32767
    const int b = p >> 12;
    const int h = (p >> 6) & 63;
    const int w = p & 63;

    float acc[64];
#pragma unroll
    for (int o = 0; o < 64; ++o) acc[o] = 0.0f;

    const float* offb = g_off + (size_t)b * COFF_ * HW_ + h * W_ + w;
    const float* inb  = in + (size_t)b * C_ * HW_;

    for (int cg = 0; cg < CG_; ++cg) {
        for (int k = 0; k < K_; ++k) {
            const int ky = k / 3, kx = k % 3;
            const int base = cg * K_ + k;

            float dyv[4], dxv[4], lg[4];
#pragma unroll
            for (int g = 0; g < 4; ++g) {
                int ch = g * KKN + base;                 // index within 576-channel field
                dyv[g] = __ldg(offb + (size_t)ch * HW_);
                dxv[g] = __ldg(offb + (size_t)(576 + ch) * HW_);
                lg[g]  = __ldg(offb + (size_t)(1152 + ch) * HW_);
            }
            // softmax over groups
            float m = fmaxf(fmaxf(lg[0], lg[1]), fmaxf(lg[2], lg[3]));
            float e[4];
#pragma unroll
            for (int g = 0; g < 4; ++g) e[g] = __expf(lg[g] - m);
            float inv = __fdividef(1.0f, e[0] + e[1] + e[2] + e[3]);

#pragma unroll
            for (int g = 0; g < 4; ++g) {
                float mask = e[g] * inv;
                // sample position in padded coords; input coord = padded - 1
                float py = (float)(h + ky) + dyv[g];
                float px = (float)(w + kx) + dxv[g];
                float y0 = floorf(py);
                float x0 = floorf(px);
                float wy = py - y0;
                float wx = px - x0;
                int iy = (int)y0 - 1;
                int ix = (int)x0 - 1;
                const float* cin = inb + (g * CG_ + cg) * HW_;

                bool yv0 = (unsigned)iy < (unsigned)H_;
                bool yv1 = (unsigned)(iy + 1) < (unsigned)H_;
                bool xv0 = (unsigned)ix < (unsigned)W_;
                bool xv1 = (unsigned)(ix + 1) < (unsigned)W_;
                float v00 = (yv0 && xv0) ? __ldg(cin + iy * W_ + ix) : 0.0f;
                float v01 = (yv0 && xv1) ? __ldg(cin + iy * W_ + ix + 1) : 0.0f;
                float v10 = (yv1 && xv0) ? __ldg(cin + (iy + 1) * W_ + ix) : 0.0f;
                float v11 = (yv1 && xv1) ? __ldg(cin + (iy + 1) * W_ + ix + 1) : 0.0f;

                float val = ((1.0f - wy) * (1.0f - wx) * v00 +
                             (1.0f - wy) * wx * v01 +
                             wy * (1.0f - wx) * v10 +
                             wy * wx * v11) * mask;

                const float* wr = &sW[((g * CG_ + cg) * K_ + k) * 16];
#pragma unroll
                for (int ol = 0; ol < 16; ++ol)
                    acc[g * 16 + ol] = fmaf(wr[ol], val, acc[g * 16 + ol]);
            }
        }
    }

    float* outp = (float*)nullptr;  // set below via param-free trick? -> use global param instead
    (void)outp;
    // store happens via the out pointer passed through constant: see wrapper below
    // (we store directly here using the out pointer in .param — declared next)
    extern __device__ float* g_out_ptr_unused;  // (not used)
}

// The store needs d_out; simplest is to pass it as a kernel parameter.
// Re-declare kernel 2 properly with the out pointer (the version above without
// store is unused).  To keep a single definition, we implement the real kernel
// here and the one above is never launched.
__global__ __launch_bounds__(128) void deform_main_kernel2(
    const float* __restrict__ in,
    const float* __restrict__ wmain,
    const float* __restrict__ bias,
    float* __restrict__ out)
{
    __shared__ float sW[G_ * CG_ * K_ * 16];

    for (int i = threadIdx.x; i < 64 * KKN; i += 128) {
        int o  = i / KKN;
        int r  = i % KKN;
        int gq = o >> 4, ol = o & 15;
        int cg = r / K_, k = r % K_;
        sW[((gq * CG_ + cg) * K_ + k) * 16 + ol] = wmain[o * KKN + r];
    }
    __syncthreads();

    const int p = blockIdx.x * 128 + threadIdx.x;
    const int b = p >> 12;
    const int h = (p >> 6) & 63;
    const int w = p & 63;

    float acc[64];
#pragma unroll
    for (int o = 0; o < 64; ++o) acc[o] = 0.0f;

    const float* offb = g_off + (size_t)b * COFF_ * HW_ + h * W_ + w;
    const float* inb  = in + (size_t)b * C_ * HW_;

    for (int cg = 0; cg < CG_; ++cg) {
        for (int k = 0; k < K_; ++k) {
            const int ky = k / 3, kx = k % 3;
            const int base = cg * K_ + k;

            float dyv[4], dxv[4], lg[4];
#pragma unroll
            for (int g = 0; g < 4; ++g) {
                int ch = g * KKN + base;
                dyv[g] = __ldg(offb + (size_t)ch * HW_);
                dxv[g] = __ldg(offb + (size_t)(576 + ch) * HW_);
                lg[g]  = __ldg(offb + (size_t)(1152 + ch) * HW_);
            }
            float m = fmaxf(fmaxf(lg[0], lg[1]), fmaxf(lg[2], lg[3]));
            float e[4];
#pragma unroll
            for (int g = 0; g < 4; ++g) e[g] = __expf(lg[g] - m);
            float inv = __fdividef(1.0f, e[0] + e[1] + e[2] + e[3]);

#pragma unroll
            for (int g = 0; g < 4; ++g) {
                float mask = e[g] * inv;
                float py = (float)(h + ky) + dyv[g];
                float px = (float)(w + kx) + dxv[g];
                float y0 = floorf(py);
                float x0 = floorf(px);
                float wy = py - y0;
                float wx = px - x0;
                int iy = (int)y0 - 1;
                int ix = (int)x0 - 1;
                const float* cin = inb + (g * CG_ + cg) * HW_;

                bool yv0 = (unsigned)iy < (unsigned)H_;
                bool yv1 = (unsigned)(iy + 1) < (unsigned)H_;
                bool xv0 = (unsigned)ix < (unsigned)W_;
                bool xv1 = (unsigned)(ix + 1) < (unsigned)W_;
                float v00 = (yv0 && xv0) ? __ldg(cin + iy * W_ + ix) : 0.0f;
                float v01 = (yv0 && xv1) ? __ldg(cin + iy * W_ + ix + 1) : 0.0f;
                float v10 = (yv1 && xv0) ? __ldg(cin + (iy + 1) * W_ + ix) : 0.0f;
                float v11 = (yv1 && xv1) ? __ldg(cin + (iy + 1) * W_ + ix + 1) : 0.0f;

                float val = ((1.0f - wy) * (1.0f - wx) * v00 +
                             (1.0f - wy) * wx * v01 +
                             wy * (1.0f - wx) * v10 +
                             wy * wx * v11) * mask;

                const float* wr = &sW[((g * CG_ + cg) * K_ + k) * 16];
#pragma unroll
                for (int ol = 0; ol < 16; ++ol)
                    acc[g * 16 + ol] = fmaf(wr[ol], val, acc[g * 16 + ol]);
            }
        }
    }

#pragma unroll
    for (int o = 0; o < 64; ++o)
        out[((size_t)(b * 64 + o)) * HW_ + h * W_ + w] = acc[o] + __ldg(bias + o);
}

// ---------------------------------------------------------------------------
extern "C" void kernel_launch(void* const* d_in, const int* in_sizes, int n_in,
                              void* d_out, int out_size) {
    const float* inps   = (const float*)d_in[0];  // 8*64*64*64
    const float* weight = (const float*)d_in[1];  // 64*16*3*3
    const float* bias   = (const float*)d_in[2];  // 64
    const float* w_off  = (const float*)d_in[3];  // 1728*16*3*3
    const float* b_off  = (const float*)d_in[4];  // 1728
    float* out = (float*)d_out;

    const int smem1 = (KKN * PXT + KKN * OCT) * (int)sizeof(float);  // 175104 B
    cudaFuncSetAttribute(off_conv_kernel, cudaFuncAttributeMaxDynamicSharedMemorySize, smem1);

    off_conv_kernel<<<dim3(16, 36, B_), 256, smem1>>>(inps, w_off, b_off);
    deform_main_kernel2<<<(B_ * HW_) / 128, 128>>>(inps, weight, bias, out);
}

// round 4
// speedup vs baseline: 1.6548x; 1.6548x over previous
#include <cuda_runtime.h>
#include <cuda_bf16.h>
#include <cstdint>

// DeformConv2d B=8 C=64 H=W=64 G=4 3x3 pad1  (sm_100 base target: mma.sync path)
// K1: offset conv 64->1728 via bf16-split mma.sync GEMM, scratch [b][px][1728].
// K2: softmax + bilinear + grouped main conv, thread per (pixel, group).

__device__ float g_off2[(size_t)8 * 4096 * 1728];   // 226 MB scratch

// ---- smem geometry (bf16 elements, stride 296 = 288 data + 8 pad) ----
#define SASTRIDE 296
#define SA_BYTES (128 * SASTRIDE * 2)      // 75776
#define SB_BYTES (144 * SASTRIDE * 2)      // 85248
#define SM_TOT   (SA_BYTES + SB_BYTES)     // 161024

__device__ __forceinline__ uint32_t smem_u32(const void* p) {
    uint32_t a;
    asm("{ .reg .u64 t; cvta.to.shared.u64 t, %1; cvt.u32.u64 %0, t; }" : "=r"(a) : "l"(p));
    return a;
}

__device__ __forceinline__ void ldmA(uint32_t* r, uint32_t addr) {
    asm volatile("ldmatrix.sync.aligned.m8n8.x4.shared.b16 {%0,%1,%2,%3}, [%4];"
                 : "=r"(r[0]), "=r"(r[1]), "=r"(r[2]), "=r"(r[3]) : "r"(addr));
}
__device__ __forceinline__ void ldmB4(uint32_t* r, uint32_t addr) {
    asm volatile("ldmatrix.sync.aligned.m8n8.x4.shared.b16 {%0,%1,%2,%3}, [%4];"
                 : "=r"(r[0]), "=r"(r[1]), "=r"(r[2]), "=r"(r[3]) : "r"(addr));
}
__device__ __forceinline__ void ldmB2(uint32_t* r, uint32_t addr) {
    asm volatile("ldmatrix.sync.aligned.m8n8.x2.shared.b16 {%0,%1}, [%2];"
                 : "=r"(r[0]), "=r"(r[1]) : "r"(addr));
}
__device__ __forceinline__ void mma16816(float* d, const uint32_t* a, const uint32_t* b) {
    asm volatile("mma.sync.aligned.m16n8k16.row.col.f32.bf16.bf16.f32 "
                 "{%0,%1,%2,%3}, {%4,%5,%6,%7}, {%8,%9}, {%0,%1,%2,%3};"
                 : "+f"(d[0]), "+f"(d[1]), "+f"(d[2]), "+f"(d[3])
                 : "r"(a[0]), "r"(a[1]), "r"(a[2]), "r"(a[3]), "r"(b[0]), "r"(b[1]));
}

__device__ __forceinline__ void split1(float v, __nv_bfloat16& hi, __nv_bfloat16& lo) {
    hi = __float2bfloat16_rn(v);
    lo = __float2bfloat16_rn(v - __bfloat162float(hi));
}

// ---------------------------------------------------------------------------
// K1: grid (32 px-tiles, 12 = g*3+sub, 8 batch), block 256 (8 warps).
// ---------------------------------------------------------------------------
__global__ void __launch_bounds__(256) off_conv_mma(
    const float* __restrict__ in, const float* __restrict__ w_off,
    const float* __restrict__ b_off)
{
    extern __shared__ char smem[];
    __nv_bfloat16* sA = (__nv_bfloat16*)smem;
    __nv_bfloat16* sB = (__nv_bfloat16*)(smem + SA_BYTES);
    const uint32_t sAu = smem_u32(sA), sBu = smem_u32(sB);

    const int tid = threadIdx.x, wid = tid >> 5, lane = tid & 31;
    const int pxt = blockIdx.x, b = blockIdx.z;
    const int g = blockIdx.y / 3, sub = blockIdx.y % 3;
    const int oc0 = g * 432 + sub * 144;
    const int h0 = pxt * 2;

    // ---- fill A: im2col X[128 px][144 k] -> hi at k, lo at 144+k ----
    const float* inb = in + ((size_t)(b * 64 + g * 16)) * 4096;
    for (int i = tid; i < 128 * 144; i += 256) {
        int m = i / 144, k = i % 144;
        int cg = k / 9, t = k % 9;
        int h = h0 + (m >> 6), w = m & 63;
        int ih = h - 1 + t / 3, iw = w - 1 + t % 3;
        float v = ((unsigned)ih < 64u && (unsigned)iw < 64u)
                  ? __ldg(inb + cg * 4096 + ih * 64 + iw) : 0.f;
        __nv_bfloat16 hi, lo; split1(v, hi, lo);
        sA[m * SASTRIDE + k] = hi;
        sA[m * SASTRIDE + 144 + k] = lo;
    }
    // ---- fill B: W[144 oc][144 k] ----
    for (int i = tid; i < 144 * 144; i += 256) {
        int n = i / 144, k = i % 144;
        float v = __ldg(w_off + (size_t)(oc0 + n) * 144 + k);
        __nv_bfloat16 hi, lo; split1(v, hi, lo);
        sB[n * SASTRIDE + k] = hi;
        sB[n * SASTRIDE + 144 + k] = lo;
    }
    __syncthreads();

    // ---- warp tiles: 4 along M (32 rows), 2 along N (72 cols) ----
    const int wm = wid & 3, wn = wid >> 2;
    const int m_base = wm * 32, n_base = wn * 72;

    float acc[2][9][4];
#pragma unroll
    for (int i = 0; i < 2; ++i)
#pragma unroll
        for (int j = 0; j < 9; ++j)
#pragma unroll
            for (int q = 0; q < 4; ++q) acc[i][j][q] = 0.f;

    // precomputed lane pieces
    const int aRow = lane & 15, aColSel = (lane >> 4) << 3;           // A addr parts
    const int bNlane = ((lane >> 4) << 3) + (lane & 7);               // B n offset
    const int bKlane = ((lane >> 3) & 1) << 3;                        // B k offset

#pragma unroll
    for (int term = 0; term < 3; ++term) {
        const int kAoff = (term == 2) ? 144 : 0;
        const int kBoff = (term == 1) ? 144 : 0;
#pragma unroll 3
        for (int j = 0; j < 9; ++j) {
            const int kA = kAoff + j * 16, kB = kBoff + j * 16;
            uint32_t afr[2][4];
#pragma unroll
            for (int mf = 0; mf < 2; ++mf) {
                uint32_t addr = sAu + ((m_base + mf * 16 + aRow) * SASTRIDE + kA + aColSel) * 2;
                ldmA(afr[mf], addr);
            }
            uint32_t bfr[9][2];
#pragma unroll
            for (int pr = 0; pr < 4; ++pr) {
                uint32_t tmp[4];
                uint32_t addr = sBu + ((n_base + pr * 16 + bNlane) * SASTRIDE + kB + bKlane) * 2;
                ldmB4(tmp, addr);
                bfr[pr * 2][0] = tmp[0]; bfr[pr * 2][1] = tmp[1];
                bfr[pr * 2 + 1][0] = tmp[2]; bfr[pr * 2 + 1][1] = tmp[3];
            }
            {
                uint32_t addr = sBu + ((n_base + 64 + (lane & 7)) * SASTRIDE + kB + bKlane) * 2;
                ldmB2(bfr[8], addr);
            }
#pragma unroll
            for (int mf = 0; mf < 2; ++mf)
#pragma unroll
                for (int nf = 0; nf < 9; ++nf)
                    mma16816(acc[mf][nf], afr[mf], bfr[nf]);
        }
    }
    __syncthreads();

    // ---- stage accums into smem as float [128][148] ----
    float* sAf = (float*)smem;
    {
        const int r0l = lane >> 2, c0l = (lane & 3) * 2;
#pragma unroll
        for (int mf = 0; mf < 2; ++mf) {
#pragma unroll
            for (int nf = 0; nf < 9; ++nf) {
                int r0 = m_base + mf * 16 + r0l;
                int c = n_base + nf * 8 + c0l;
                *(float2*)&sAf[r0 * 148 + c] = make_float2(acc[mf][nf][0], acc[mf][nf][1]);
                *(float2*)&sAf[(r0 + 8) * 148 + c] = make_float2(acc[mf][nf][2], acc[mf][nf][3]);
            }
        }
    }
    __syncthreads();

    // ---- coalesced store + bias: 128 rows x 144 cols ----
    for (int i = tid; i < 128 * 36; i += 256) {
        int m = i / 36, q = i % 36;
        float4 v = *(float4*)&sAf[m * 148 + q * 4];
        float4 bv = *(const float4*)(b_off + oc0 + q * 4);
        v.x += bv.x; v.y += bv.y; v.z += bv.z; v.w += bv.w;
        *(float4*)(g_off2 + ((size_t)(b * 4096 + pxt * 128 + m)) * 1728 + oc0 + q * 4) = v;
    }
}

// ---------------------------------------------------------------------------
// K2: thread per (pixel, group). 131072 threads.
// ---------------------------------------------------------------------------
__global__ __launch_bounds__(256) void deform_main_k2(
    const float* __restrict__ in, const float* __restrict__ wmain,
    const float* __restrict__ bias, float* __restrict__ out)
{
    __shared__ float sW[4 * 2308];   // [g] stride 2308 x [cg*9+k][16 oc]
    for (int i = threadIdx.x; i < 64 * 144; i += 256) {
        int o = i / 144, r = i % 144;
        sW[(o >> 4) * 2308 + r * 16 + (o & 15)] = wmain[i];
    }
    __syncthreads();

    const int t = blockIdx.x * 256 + threadIdx.x;
    const int g = t & 3, p = t >> 2;
    const int b = p >> 12, h = (p >> 6) & 63, w = p & 63;

    const float* offp = g_off2 + (size_t)p * 1728 + g * 144;
    const float* cinb = in + ((size_t)(b * 64 + g * 16)) * 4096;

    float acc[16];
#pragma unroll
    for (int o = 0; o < 16; ++o) acc[o] = 0.f;

    for (int cg = 0; cg < 16; ++cg) {
#pragma unroll
        for (int k = 0; k < 9; ++k) {
            const int r = cg * 9 + k;
            float dy = __ldg(offp + r);
            float dx = __ldg(offp + 576 + r);
            float lg = __ldg(offp + 1152 + r);

            float m = lg;
            m = fmaxf(m, __shfl_xor_sync(0xFFFFFFFFu, m, 1));
            m = fmaxf(m, __shfl_xor_sync(0xFFFFFFFFu, m, 2));
            float e = __expf(lg - m);
            float s = e;
            s += __shfl_xor_sync(0xFFFFFFFFu, s, 1);
            s += __shfl_xor_sync(0xFFFFFFFFu, s, 2);
            float mask = e * __fdividef(1.f, s);

            float py = (float)(h + k / 3) + dy;
            float px = (float)(w + k % 3) + dx;
            float y0 = floorf(py), x0 = floorf(px);
            float wy = py - y0, wx = px - x0;
            int iy = (int)y0 - 1, ix = (int)x0 - 1;
            const float* cin = cinb + cg * 4096;
            bool yv0 = (unsigned)iy < 64u, yv1 = (unsigned)(iy + 1) < 64u;
            bool xv0 = (unsigned)ix < 64u, xv1 = (unsigned)(ix + 1) < 64u;
            float v00 = (yv0 && xv0) ? __ldg(cin + iy * 64 + ix) : 0.f;
            float v01 = (yv0 && xv1) ? __ldg(cin + iy * 64 + ix + 1) : 0.f;
            float v10 = (yv1 && xv0) ? __ldg(cin + (iy + 1) * 64 + ix) : 0.f;
            float v11 = (yv1 && xv1) ? __ldg(cin + (iy + 1) * 64 + ix + 1) : 0.f;
            float val = ((1.f - wy) * (1.f - wx) * v00 + (1.f - wy) * wx * v01 +
                         wy * (1.f - wx) * v10 + wy * wx * v11) * mask;

            const float4* wr = (const float4*)&sW[g * 2308 + r * 16];
            float4 w0 = wr[0], w1 = wr[1], w2 = wr[2], w3 = wr[3];
            acc[0]  = fmaf(w0.x, val, acc[0]);  acc[1]  = fmaf(w0.y, val, acc[1]);
            acc[2]  = fmaf(w0.z, val, acc[2]);  acc[3]  = fmaf(w0.w, val, acc[3]);
            acc[4]  = fmaf(w1.x, val, acc[4]);  acc[5]  = fmaf(w1.y, val, acc[5]);
            acc[6]  = fmaf(w1.z, val, acc[6]);  acc[7]  = fmaf(w1.w, val, acc[7]);
            acc[8]  = fmaf(w2.x, val, acc[8]);  acc[9]  = fmaf(w2.y, val, acc[9]);
            acc[10] = fmaf(w2.z, val, acc[10]); acc[11] = fmaf(w2.w, val, acc[11]);
            acc[12] = fmaf(w3.x, val, acc[12]); acc[13] = fmaf(w3.y, val, acc[13]);
            acc[14] = fmaf(w3.z, val, acc[14]); acc[15] = fmaf(w3.w, val, acc[15]);
        }
    }

    const int hw = p & 4095;
#pragma unroll
    for (int ol = 0; ol < 16; ++ol)
        out[((size_t)(b * 64 + g * 16 + ol)) * 4096 + hw] = acc[ol] + __ldg(bias + g * 16 + ol);
}

// ---------------------------------------------------------------------------
extern "C" void kernel_launch(void* const* d_in, const int* in_sizes, int n_in,
                              void* d_out, int out_size) {
    const float* inps   = (const float*)d_in[0];
    const float* weight = (const float*)d_in[1];
    const float* bias   = (const float*)d_in[2];
    const float* w_off  = (const float*)d_in[3];
    const float* b_off  = (const float*)d_in[4];
    float* out = (float*)d_out;

    cudaFuncSetAttribute(off_conv_mma, cudaFuncAttributeMaxDynamicSharedMemorySize, SM_TOT);
    off_conv_mma<<<dim3(32, 12, 8), 256, SM_TOT>>>(inps, w_off, b_off);
    deform_main_k2<<<512, 256>>>(inps, weight, bias, out);
}

// round 6
// speedup vs baseline: 2.9604x; 1.7890x over previous
#include <cuda_runtime.h>
#include <cuda_bf16.h>
#include <cstdint>

// DeformConv2d B=8 C=64 H=W=64 G=4 3x3 pad1 (sm_100 base, mma.sync path)
// K0: pre-split offset-conv weights to bf16 hi/lo.
// K1: offset conv via bf16-split mma.sync; scratch [b][pxblk][r][f][gs][px8].
// K2: softmax + bilinear + grouped main conv, thread per (pixel, group).

__device__ float g_off3[(size_t)8 * 512 * 144 * 96];      // 226 MB scratch
__device__ __nv_bfloat16 g_wsplit[1728 * 288];            // hi at k, lo at 144+k

// ---- smem geometry (bf16 elements, stride 296 = 288 data + 8 pad) ----
#define SASTRIDE 296
#define SA_BYTES (128 * SASTRIDE * 2)      // 75776
#define SB_BYTES (144 * SASTRIDE * 2)      // 85248
#define SM_TOT   (SA_BYTES + SB_BYTES)     // 161024

__device__ __forceinline__ uint32_t smem_u32(const void* p) {
    uint32_t a;
    asm("{ .reg .u64 t; cvta.to.shared.u64 t, %1; cvt.u32.u64 %0, t; }" : "=r"(a) : "l"(p));
    return a;
}
__device__ __forceinline__ void ldmA(uint32_t* r, uint32_t addr) {
    asm volatile("ldmatrix.sync.aligned.m8n8.x4.shared.b16 {%0,%1,%2,%3}, [%4];"
                 : "=r"(r[0]), "=r"(r[1]), "=r"(r[2]), "=r"(r[3]) : "r"(addr));
}
__device__ __forceinline__ void ldmB4(uint32_t* r, uint32_t addr) {
    asm volatile("ldmatrix.sync.aligned.m8n8.x4.shared.b16 {%0,%1,%2,%3}, [%4];"
                 : "=r"(r[0]), "=r"(r[1]), "=r"(r[2]), "=r"(r[3]) : "r"(addr));
}
__device__ __forceinline__ void ldmB2(uint32_t* r, uint32_t addr) {
    asm volatile("ldmatrix.sync.aligned.m8n8.x2.shared.b16 {%0,%1}, [%2];"
                 : "=r"(r[0]), "=r"(r[1]) : "r"(addr));
}
__device__ __forceinline__ void mma16816(float* d, const uint32_t* a, const uint32_t* b) {
    asm volatile("mma.sync.aligned.m16n8k16.row.col.f32.bf16.bf16.f32 "
                 "{%0,%1,%2,%3}, {%4,%5,%6,%7}, {%8,%9}, {%0,%1,%2,%3};"
                 : "+f"(d[0]), "+f"(d[1]), "+f"(d[2]), "+f"(d[3])
                 : "r"(a[0]), "r"(a[1]), "r"(a[2]), "r"(a[3]), "r"(b[0]), "r"(b[1]));
}
__device__ __forceinline__ void split1(float v, __nv_bfloat16& hi, __nv_bfloat16& lo) {
    hi = __float2bfloat16_rn(v);
    lo = __float2bfloat16_rn(v - __bfloat162float(hi));
}

// ---------------------------------------------------------------------------
// K0: split weights once.
// ---------------------------------------------------------------------------
__global__ __launch_bounds__(256) void split_weights(const float* __restrict__ w_off) {
    int i = blockIdx.x * 256 + threadIdx.x;
    if (i >= 1728 * 144) return;
    int oc = i / 144, k = i % 144;
    __nv_bfloat16 hi, lo;
    split1(w_off[i], hi, lo);
    g_wsplit[oc * 288 + k] = hi;
    g_wsplit[oc * 288 + 144 + k] = lo;
}

// ---------------------------------------------------------------------------
// K1: grid (32 pxt, 4 g, 8 b), block 256. A built once; sub loop internal.
// ---------------------------------------------------------------------------
__global__ void __launch_bounds__(256) off_conv_mma(
    const float* __restrict__ in, const float* __restrict__ b_off)
{
    extern __shared__ char smem[];
    __nv_bfloat16* sA = (__nv_bfloat16*)smem;
    __nv_bfloat16* sB = (__nv_bfloat16*)(smem + SA_BYTES);
    float* sBf = (float*)(smem + SA_BYTES);              // epilogue staging
    const uint32_t sAu = smem_u32(sA), sBu = smem_u32(sB);

    const int tid = threadIdx.x, wid = tid >> 5, lane = tid & 31;
    const int pxt = blockIdx.x, g = blockIdx.y, b = blockIdx.z;
    const int h0 = pxt * 2;

    // ---- A: im2col X[128 px][144 k] -> hi at k, lo at 144+k (once) ----
    const float* inb = in + ((size_t)(b * 64 + g * 16)) * 4096;
    for (int i = tid; i < 128 * 144; i += 256) {
        int m = i / 144, k = i % 144;
        int cg = k / 9, t = k % 9;
        int h = h0 + (m >> 6), w = m & 63;
        int ih = h - 1 + t / 3, iw = w - 1 + t % 3;
        float v = ((unsigned)ih < 64u && (unsigned)iw < 64u)
                  ? __ldg(inb + cg * 4096 + ih * 64 + iw) : 0.f;
        __nv_bfloat16 hi, lo; split1(v, hi, lo);
        sA[m * SASTRIDE + k] = hi;
        sA[m * SASTRIDE + 144 + k] = lo;
    }

    // lane pieces for fragments
    const int wm = wid & 3, wn = wid >> 2;
    const int m_base = wm * 32, n_base = wn * 72;
    const int aRow = lane & 15, aColSel = (lane >> 4) << 3;
    const int bNlane = ((lane >> 4) << 3) + (lane & 7);
    const int bKlane = ((lane >> 3) & 1) << 3;

    for (int sub = 0; sub < 3; ++sub) {
        const int oc0 = g * 432 + sub * 144;

        // ---- B fill: uint4 copy of pre-split rows ----
        for (int i = tid; i < 144 * 36; i += 256) {
            int n = i / 36, q = i % 36;
            uint4 v = *(const uint4*)((const char*)(g_wsplit + (size_t)(oc0 + n) * 288) + q * 16);
            *(uint4*)((char*)sB + n * (SASTRIDE * 2) + q * 16) = v;
        }
        __syncthreads();

        float acc[2][9][4];
#pragma unroll
        for (int i = 0; i < 2; ++i)
#pragma unroll
            for (int j = 0; j < 9; ++j)
#pragma unroll
                for (int q = 0; q < 4; ++q) acc[i][j][q] = 0.f;

#pragma unroll
        for (int term = 0; term < 3; ++term) {
            const int kAoff = (term == 2) ? 144 : 0;
            const int kBoff = (term == 1) ? 144 : 0;
#pragma unroll 3
            for (int j = 0; j < 9; ++j) {
                const int kA = kAoff + j * 16, kB = kBoff + j * 16;
                uint32_t afr[2][4];
#pragma unroll
                for (int mf = 0; mf < 2; ++mf) {
                    uint32_t addr = sAu + ((m_base + mf * 16 + aRow) * SASTRIDE + kA + aColSel) * 2;
                    ldmA(afr[mf], addr);
                }
                uint32_t bfr[9][2];
#pragma unroll
                for (int pr = 0; pr < 4; ++pr) {
                    uint32_t tmp[4];
                    uint32_t addr = sBu + ((n_base + pr * 16 + bNlane) * SASTRIDE + kB + bKlane) * 2;
                    ldmB4(tmp, addr);
                    bfr[pr * 2][0] = tmp[0]; bfr[pr * 2][1] = tmp[1];
                    bfr[pr * 2 + 1][0] = tmp[2]; bfr[pr * 2 + 1][1] = tmp[3];
                }
                {
                    uint32_t addr = sBu + ((n_base + 64 + (lane & 7)) * SASTRIDE + kB + bKlane) * 2;
                    ldmB2(bfr[8], addr);
                }
#pragma unroll
                for (int mf = 0; mf < 2; ++mf)
#pragma unroll
                    for (int nf = 0; nf < 9; ++nf)
                        mma16816(acc[mf][nf], afr[mf], bfr[nf]);
            }
        }
        __syncthreads();   // gemm done; sB region reused for staging

        // ---- stage accums into sBf as float [128 px][148] ----
        {
            const int r0l = lane >> 2, c0l = (lane & 3) * 2;
#pragma unroll
            for (int mf = 0; mf < 2; ++mf) {
#pragma unroll
                for (int nf = 0; nf < 9; ++nf) {
                    int r0 = m_base + mf * 16 + r0l;
                    int c = n_base + nf * 8 + c0l;
                    *(float2*)&sBf[r0 * 148 + c] = make_float2(acc[mf][nf][0], acc[mf][nf][1]);
                    *(float2*)&sBf[(r0 + 8) * 148 + c] = make_float2(acc[mf][nf][2], acc[mf][nf][3]);
                }
            }
        }
        __syncthreads();

        // ---- store to scratch [b][pxblk][r][f][gs][px8] + bias ----
        {
            const int fg = 3 * g + sub;
            const int f = fg >> 2, gs = fg & 3;
            const int px8 = tid & 7, pbl = (tid >> 3) & 15, rst = tid >> 7;
            float* basep = g_off3 + ((size_t)(b * 512 + pxt * 16 + pbl)) * 13824
                         + f * 32 + gs * 8 + px8;
            const float* srow = &sBf[(pbl * 8 + px8) * 148];
            for (int r = rst; r < 144; r += 2)
                basep[r * 96] = srow[r] + __ldg(b_off + oc0 + r);
        }
        __syncthreads();   // before next sB fill
    }
}

// ---------------------------------------------------------------------------
// K2: thread per (pixel, group). Offset reads fully coalesced.
// ---------------------------------------------------------------------------
__global__ __launch_bounds__(256) void deform_main_k2(
    const float* __restrict__ in, const float* __restrict__ wmain,
    const float* __restrict__ bias, float* __restrict__ out)
{
    __shared__ float sW[4 * 2308];   // [g] stride 2308 x [r][16 oc]
    for (int i = threadIdx.x; i < 64 * 144; i += 256) {
        int o = i / 144, r = i % 144;
        sW[(o >> 4) * 2308 + r * 16 + (o & 15)] = wmain[i];
    }
    __syncthreads();

    const int t = blockIdx.x * 256 + threadIdx.x;
    const int g = t & 3, p = t >> 2;
    const int b = p >> 12, h = (p >> 6) & 63, w = p & 63;

    // FIXED: p>>3 already includes the batch (p = b*4096 + hw)
    const float* offb = g_off3 + (size_t)(p >> 3) * 13824 + g * 8 + (p & 7);
    const float* cinb = in + ((size_t)(b * 64 + g * 16)) * 4096;

    float acc[16];
#pragma unroll
    for (int o = 0; o < 16; ++o) acc[o] = 0.f;

    for (int cg = 0; cg < 16; ++cg) {
#pragma unroll
        for (int k = 0; k < 9; ++k) {
            const int r = cg * 9 + k;
            float dy = __ldg(offb + r * 96);
            float dx = __ldg(offb + r * 96 + 32);
            float lg = __ldg(offb + r * 96 + 64);

            float m = lg;
            m = fmaxf(m, __shfl_xor_sync(0xFFFFFFFFu, m, 1));
            m = fmaxf(m, __shfl_xor_sync(0xFFFFFFFFu, m, 2));
            float e = __expf(lg - m);
            float s = e;
            s += __shfl_xor_sync(0xFFFFFFFFu, s, 1);
            s += __shfl_xor_sync(0xFFFFFFFFu, s, 2);
            float mask = e * __fdividef(1.f, s);

            float py = (float)(h + k / 3) + dy;
            float px = (float)(w + k % 3) + dx;
            float y0 = floorf(py), x0 = floorf(px);
            float wy = py - y0, wx = px - x0;
            int iy = (int)y0 - 1, ix = (int)x0 - 1;
            const float* cin = cinb + cg * 4096;
            bool yv0 = (unsigned)iy < 64u, yv1 = (unsigned)(iy + 1) < 64u;
            bool xv0 = (unsigned)ix < 64u, xv1 = (unsigned)(ix + 1) < 64u;
            float v00 = (yv0 && xv0) ? __ldg(cin + iy * 64 + ix) : 0.f;
            float v01 = (yv0 && xv1) ? __ldg(cin + iy * 64 + ix + 1) : 0.f;
            float v10 = (yv1 && xv0) ? __ldg(cin + (iy + 1) * 64 + ix) : 0.f;
            float v11 = (yv1 && xv1) ? __ldg(cin + (iy + 1) * 64 + ix + 1) : 0.f;
            float val = ((1.f - wy) * (1.f - wx) * v00 + (1.f - wy) * wx * v01 +
                         wy * (1.f - wx) * v10 + wy * wx * v11) * mask;

            const float4* wr = (const float4*)&sW[g * 2308 + r * 16];
            float4 w0 = wr[0], w1 = wr[1], w2 = wr[2], w3 = wr[3];
            acc[0]  = fmaf(w0.x, val, acc[0]);  acc[1]  = fmaf(w0.y, val, acc[1]);
            acc[2]  = fmaf(w0.z, val, acc[2]);  acc[3]  = fmaf(w0.w, val, acc[3]);
            acc[4]  = fmaf(w1.x, val, acc[4]);  acc[5]  = fmaf(w1.y, val, acc[5]);
            acc[6]  = fmaf(w1.z, val, acc[6]);  acc[7]  = fmaf(w1.w, val, acc[7]);
            acc[8]  = fmaf(w2.x, val, acc[8]);  acc[9]  = fmaf(w2.y, val, acc[9]);
            acc[10] = fmaf(w2.z, val, acc[10]); acc[11] = fmaf(w2.w, val, acc[11]);
            acc[12] = fmaf(w3.x, val, acc[12]); acc[13] = fmaf(w3.y, val, acc[13]);
            acc[14] = fmaf(w3.z, val, acc[14]); acc[15] = fmaf(w3.w, val, acc[15]);
        }
    }

    const int hw = p & 4095;
#pragma unroll
    for (int ol = 0; ol < 16; ++ol)
        out[((size_t)(b * 64 + g * 16 + ol)) * 4096 + hw] = acc[ol] + __ldg(bias + g * 16 + ol);
}

// ---------------------------------------------------------------------------
extern "C" void kernel_launch(void* const* d_in, const int* in_sizes, int n_in,
                              void* d_out, int out_size) {
    const float* inps   = (const float*)d_in[0];
    const float* weight = (const float*)d_in[1];
    const float* bias   = (const float*)d_in[2];
    const float* w_off  = (const float*)d_in[3];
    const float* b_off  = (const float*)d_in[4];
    float* out = (float*)d_out;

    cudaFuncSetAttribute(off_conv_mma, cudaFuncAttributeMaxDynamicSharedMemorySize, SM_TOT);
    split_weights<<<(1728 * 144 + 255) / 256, 256>>>(w_off);
    off_conv_mma<<<dim3(32, 4, 8), 256, SM_TOT>>>(inps, b_off);
    deform_main_k2<<<512, 256>>>(inps, weight, bias, out);
}

// round 7
// speedup vs baseline: 3.0643x; 1.0351x over previous
#include <cuda_runtime.h>
#include <cuda_bf16.h>
#include <cstdint>

// DeformConv2d B=8 C=64 H=W=64 G=4 3x3 pad1 (sm_100 base, mma.sync path)
// K0: pre-split offset-conv weights to bf16 hi/lo.
// K1: offset conv via bf16-split mma.sync; direct-register epilogue;
//     cp.async B fill overlapped with stores. Scratch [b][pxblk][r][f][gs][px8].
// K2: softmax + bilinear + grouped main conv, thread per (pixel, group).

__device__ float g_off3[(size_t)8 * 512 * 144 * 96];      // 226 MB scratch
__device__ __nv_bfloat16 g_wsplit[1728 * 288];            // hi at k, lo at 144+k

// ---- smem geometry (bf16 elements, stride 296 = 288 data + 8 pad) ----
#define SASTRIDE 296
#define SA_BYTES (128 * SASTRIDE * 2)      // 75776
#define SB_BYTES (144 * SASTRIDE * 2)      // 85248
#define SM_TOT   (SA_BYTES + SB_BYTES)     // 161024

__device__ __forceinline__ uint32_t smem_u32(const void* p) {
    uint32_t a;
    asm("{ .reg .u64 t; cvta.to.shared.u64 t, %1; cvt.u32.u64 %0, t; }" : "=r"(a) : "l"(p));
    return a;
}
__device__ __forceinline__ void ldmA(uint32_t* r, uint32_t addr) {
    asm volatile("ldmatrix.sync.aligned.m8n8.x4.shared.b16 {%0,%1,%2,%3}, [%4];"
                 : "=r"(r[0]), "=r"(r[1]), "=r"(r[2]), "=r"(r[3]) : "r"(addr));
}
__device__ __forceinline__ void ldmB4(uint32_t* r, uint32_t addr) {
    asm volatile("ldmatrix.sync.aligned.m8n8.x4.shared.b16 {%0,%1,%2,%3}, [%4];"
                 : "=r"(r[0]), "=r"(r[1]), "=r"(r[2]), "=r"(r[3]) : "r"(addr));
}
__device__ __forceinline__ void ldmB2(uint32_t* r, uint32_t addr) {
    asm volatile("ldmatrix.sync.aligned.m8n8.x2.shared.b16 {%0,%1}, [%2];"
                 : "=r"(r[0]), "=r"(r[1]) : "r"(addr));
}
__device__ __forceinline__ void mma16816(float* d, const uint32_t* a, const uint32_t* b) {
    asm volatile("mma.sync.aligned.m16n8k16.row.col.f32.bf16.bf16.f32 "
                 "{%0,%1,%2,%3}, {%4,%5,%6,%7}, {%8,%9}, {%0,%1,%2,%3};"
                 : "+f"(d[0]), "+f"(d[1]), "+f"(d[2]), "+f"(d[3])
                 : "r"(a[0]), "r"(a[1]), "r"(a[2]), "r"(a[3]), "r"(b[0]), "r"(b[1]));
}
__device__ __forceinline__ void split1(float v, __nv_bfloat16& hi, __nv_bfloat16& lo) {
    hi = __float2bfloat16_rn(v);
    lo = __float2bfloat16_rn(v - __bfloat162float(hi));
}
__device__ __forceinline__ void cp_async16(uint32_t dst, const void* src) {
    asm volatile("cp.async.cg.shared.global [%0], [%1], 16;" :: "r"(dst), "l"(src));
}
__device__ __forceinline__ void cp_commit() { asm volatile("cp.async.commit_group;"); }
__device__ __forceinline__ void cp_wait0()  { asm volatile("cp.async.wait_group 0;" ::: "memory"); }

// ---------------------------------------------------------------------------
// K0: split weights once.
// ---------------------------------------------------------------------------
__global__ __launch_bounds__(256) void split_weights(const float* __restrict__ w_off) {
    int i = blockIdx.x * 256 + threadIdx.x;
    if (i >= 1728 * 144) return;
    int oc = i / 144, k = i % 144;
    __nv_bfloat16 hi, lo;
    split1(w_off[i], hi, lo);
    g_wsplit[oc * 288 + k] = hi;
    g_wsplit[oc * 288 + 144 + k] = lo;
}

// ---------------------------------------------------------------------------
// K1: grid (32 pxt, 4 g, 8 b), block 256.
// ---------------------------------------------------------------------------
__global__ void __launch_bounds__(256) off_conv_mma(
    const float* __restrict__ in, const float* __restrict__ b_off)
{
    extern __shared__ char smem[];
    __shared__ int tabl[144];                 // (cg<<16)|(ky<<8)|kx
    __nv_bfloat16* sA = (__nv_bfloat16*)smem;
    __nv_bfloat16* sB = (__nv_bfloat16*)(smem + SA_BYTES);
    const uint32_t sAu = smem_u32(sA), sBu = smem_u32(sB);

    const int tid = threadIdx.x, wid = tid >> 5, lane = tid & 31;
    const int pxt = blockIdx.x, g = blockIdx.y, b = blockIdx.z;
    const int h0 = pxt * 2;

    if (tid < 144) {
        int cg = tid / 9, t = tid % 9;
        tabl[tid] = (cg << 16) | ((t / 3) << 8) | (t % 3);
    }

    // ---- issue B fill for sub=0 via cp.async ----
    {
        const int oc0 = g * 432;
        for (int i = tid; i < 144 * 36; i += 256) {
            int n = i / 36, q = i % 36;
            cp_async16(sBu + n * (SASTRIDE * 2) + q * 16,
                       (const char*)(g_wsplit + (size_t)(oc0 + n) * 288) + q * 16);
        }
        cp_commit();
    }
    __syncthreads();   // table visible

    // ---- A: im2col X[128 px][144 k] -> hi at k, lo at 144+k ----
    {
        const float* inb = in + ((size_t)(b * 64 + g * 16)) * 4096;
        const int m = tid >> 1;
        const int k0 = (tid & 1) * 72;
        const int h = h0 + (m >> 6), w = m & 63;
        __nv_bfloat16* rowp = sA + m * SASTRIDE;
#pragma unroll 8
        for (int j = 0; j < 72; ++j) {
            int k = k0 + j;
            int e = tabl[k];
            int cg = e >> 16, ky = (e >> 8) & 255, kx = e & 255;
            int ih = h - 1 + ky, iw = w - 1 + kx;
            float v = ((unsigned)ih < 64u && (unsigned)iw < 64u)
                      ? __ldg(inb + cg * 4096 + ih * 64 + iw) : 0.f;
            __nv_bfloat16 hi, lo; split1(v, hi, lo);
            rowp[k] = hi;
            rowp[144 + k] = lo;
        }
    }
    cp_wait0();
    __syncthreads();

    // lane pieces for fragments
    const int wm = wid & 3, wn = wid >> 2;
    const int m_base = wm * 32, n_base = wn * 72;
    const int aRow = lane & 15, aColSel = (lane >> 4) << 3;
    const int bNlane = ((lane >> 4) << 3) + (lane & 7);
    const int bKlane = ((lane >> 3) & 1) << 3;

    for (int sub = 0; sub < 3; ++sub) {
        const int oc0 = g * 432 + sub * 144;

        float acc[2][9][4];
#pragma unroll
        for (int i = 0; i < 2; ++i)
#pragma unroll
            for (int j = 0; j < 9; ++j)
#pragma unroll
                for (int q = 0; q < 4; ++q) acc[i][j][q] = 0.f;

#pragma unroll
        for (int term = 0; term < 3; ++term) {
            const int kAoff = (term == 2) ? 144 : 0;
            const int kBoff = (term == 1) ? 144 : 0;
#pragma unroll 3
            for (int j = 0; j < 9; ++j) {
                const int kA = kAoff + j * 16, kB = kBoff + j * 16;
                uint32_t afr[2][4];
#pragma unroll
                for (int mf = 0; mf < 2; ++mf) {
                    uint32_t addr = sAu + ((m_base + mf * 16 + aRow) * SASTRIDE + kA + aColSel) * 2;
                    ldmA(afr[mf], addr);
                }
                uint32_t bfr[9][2];
#pragma unroll
                for (int pr = 0; pr < 4; ++pr) {
                    uint32_t tmp[4];
                    uint32_t addr = sBu + ((n_base + pr * 16 + bNlane) * SASTRIDE + kB + bKlane) * 2;
                    ldmB4(tmp, addr);
                    bfr[pr * 2][0] = tmp[0]; bfr[pr * 2][1] = tmp[1];
                    bfr[pr * 2 + 1][0] = tmp[2]; bfr[pr * 2 + 1][1] = tmp[3];
                }
                {
                    uint32_t addr = sBu + ((n_base + 64 + (lane & 7)) * SASTRIDE + kB + bKlane) * 2;
                    ldmB2(bfr[8], addr);
                }
#pragma unroll
                for (int mf = 0; mf < 2; ++mf)
#pragma unroll
                    for (int nf = 0; nf < 9; ++nf)
                        mma16816(acc[mf][nf], afr[mf], bfr[nf]);
            }
        }
        __syncthreads();   // all warps done reading sB

        // ---- overlap: issue next sub's B fill while storing epilogue ----
        if (sub < 2) {
            const int oc1 = oc0 + 144;
            for (int i = tid; i < 144 * 36; i += 256) {
                int n = i / 36, q = i % 36;
                cp_async16(sBu + n * (SASTRIDE * 2) + q * 16,
                           (const char*)(g_wsplit + (size_t)(oc1 + n) * 288) + q * 16);
            }
            cp_commit();
        }

        // ---- direct-register epilogue: scratch [b][pxblk][r][f][gs][px8] ----
        {
            const int fg = 3 * g + sub;
            const int f = fg >> 2, gs = fg & 3;
            float* base = g_off3 + ((size_t)(b * 512 + pxt * 16)) * 13824 + f * 32 + gs * 8;
            const int r0 = n_base + ((lane & 3) << 1);
            const int pxa = m_base + (lane >> 2);
#pragma unroll
            for (int nf = 0; nf < 9; ++nf) {
                const int r = r0 + nf * 8;
                float2 bv = *(const float2*)(b_off + oc0 + r);
                float* pr_ = base + (size_t)r * 96;
#pragma unroll
                for (int mf = 0; mf < 2; ++mf) {
                    int pa = pxa + mf * 16;
                    float* p0 = pr_ + (pa >> 3) * 13824 + (pa & 7);
                    p0[0]       = acc[mf][nf][0] + bv.x;
                    p0[96]      = acc[mf][nf][1] + bv.y;
                    int pb = pa + 8;
                    float* p1 = pr_ + (pb >> 3) * 13824 + (pb & 7);
                    p1[0]       = acc[mf][nf][2] + bv.x;
                    p1[96]      = acc[mf][nf][3] + bv.y;
                }
            }
        }

        cp_wait0();
        __syncthreads();   // fresh sB ready
    }
}

// ---------------------------------------------------------------------------
// K2: thread per (pixel, group). Offset reads coalesced + streaming.
// ---------------------------------------------------------------------------
__global__ __launch_bounds__(256, 3) void deform_main_k2(
    const float* __restrict__ in, const float* __restrict__ wmain,
    const float* __restrict__ bias, float* __restrict__ out)
{
    __shared__ float sW[4 * 2308];   // [g] stride 2308 x [r][16 oc]
    for (int i = threadIdx.x; i < 64 * 144; i += 256) {
        int o = i / 144, r = i % 144;
        sW[(o >> 4) * 2308 + r * 16 + (o & 15)] = wmain[i];
    }
    __syncthreads();

    const int t = blockIdx.x * 256 + threadIdx.x;
    const int g = t & 3, p = t >> 2;
    const int b = p >> 12, h = (p >> 6) & 63, w = p & 63;

    const float* offb = g_off3 + (size_t)(p >> 3) * 13824 + g * 8 + (p & 7);
    const float* cinb = in + ((size_t)(b * 64 + g * 16)) * 4096;

    float acc[16];
#pragma unroll
    for (int o = 0; o < 16; ++o) acc[o] = 0.f;

    for (int cg = 0; cg < 16; ++cg) {
#pragma unroll
        for (int k = 0; k < 9; ++k) {
            const int r = cg * 9 + k;
            float dy = __ldcs(offb + r * 96);
            float dx = __ldcs(offb + r * 96 + 32);
            float lg = __ldcs(offb + r * 96 + 64);

            float m = lg;
            m = fmaxf(m, __shfl_xor_sync(0xFFFFFFFFu, m, 1));
            m = fmaxf(m, __shfl_xor_sync(0xFFFFFFFFu, m, 2));
            float e = __expf(lg - m);
            float s = e;
            s += __shfl_xor_sync(0xFFFFFFFFu, s, 1);
            s += __shfl_xor_sync(0xFFFFFFFFu, s, 2);
            float mask = e * __fdividef(1.f, s);

            float py = (float)(h + k / 3) + dy;
            float px = (float)(w + k % 3) + dx;
            float y0 = floorf(py), x0 = floorf(px);
            float wy = py - y0, wx = px - x0;
            int iy = (int)y0 - 1, ix = (int)x0 - 1;
            const float* cin = cinb + cg * 4096;
            bool yv0 = (unsigned)iy < 64u, yv1 = (unsigned)(iy + 1) < 64u;
            bool xv0 = (unsigned)ix < 64u, xv1 = (unsigned)(ix + 1) < 64u;
            float v00 = (yv0 && xv0) ? __ldg(cin + iy * 64 + ix) : 0.f;
            float v01 = (yv0 && xv1) ? __ldg(cin + iy * 64 + ix + 1) : 0.f;
            float v10 = (yv1 && xv0) ? __ldg(cin + (iy + 1) * 64 + ix) : 0.f;
            float v11 = (yv1 && xv1) ? __ldg(cin + (iy + 1) * 64 + ix + 1) : 0.f;
            float val = ((1.f - wy) * (1.f - wx) * v00 + (1.f - wy) * wx * v01 +
                         wy * (1.f - wx) * v10 + wy * wx * v11) * mask;

            const float4* wr = (const float4*)&sW[g * 2308 + r * 16];
            float4 w0 = wr[0], w1 = wr[1], w2 = wr[2], w3 = wr[3];
            acc[0]  = fmaf(w0.x, val, acc[0]);  acc[1]  = fmaf(w0.y, val, acc[1]);
            acc[2]  = fmaf(w0.z, val, acc[2]);  acc[3]  = fmaf(w0.w, val, acc[3]);
            acc[4]  = fmaf(w1.x, val, acc[4]);  acc[5]  = fmaf(w1.y, val, acc[5]);
            acc[6]  = fmaf(w1.z, val, acc[6]);  acc[7]  = fmaf(w1.w, val, acc[7]);
            acc[8]  = fmaf(w2.x, val, acc[8]);  acc[9]  = fmaf(w2.y, val, acc[9]);
            acc[10] = fmaf(w2.z, val, acc[10]); acc[11] = fmaf(w2.w, val, acc[11]);
            acc[12] = fmaf(w3.x, val, acc[12]); acc[13] = fmaf(w3.y, val, acc[13]);
            acc[14] = fmaf(w3.z, val, acc[14]); acc[15] = fmaf(w3.w, val, acc[15]);
        }
    }

    const int hw = p & 4095;
#pragma unroll
    for (int ol = 0; ol < 16; ++ol)
        out[((size_t)(b * 64 + g * 16 + ol)) * 4096 + hw] = acc[ol] + __ldg(bias + g * 16 + ol);
}

// ---------------------------------------------------------------------------
extern "C" void kernel_launch(void* const* d_in, const int* in_sizes, int n_in,
                              void* d_out, int out_size) {
    const float* inps   = (const float*)d_in[0];
    const float* weight = (const float*)d_in[1];
    const float* bias   = (const float*)d_in[2];
    const float* w_off  = (const float*)d_in[3];
    const float* b_off  = (const float*)d_in[4];
    float* out = (float*)d_out;

    cudaFuncSetAttribute(off_conv_mma, cudaFuncAttributeMaxDynamicSharedMemorySize, SM_TOT);
    split_weights<<<(1728 * 144 + 255) / 256, 256>>>(w_off);
    off_conv_mma<<<dim3(32, 4, 8), 256, SM_TOT>>>(inps, b_off);
    deform_main_k2<<<512, 256>>>(inps, weight, bias, out);
}

// round 10
// speedup vs baseline: 3.2305x; 1.0542x over previous
#include <cuda_runtime.h>
#include <cuda_bf16.h>
#include <cstdint>

// DeformConv2d B=8 C=64 H=W=64 G=4 3x3 pad1 (sm_100 base, mma.sync path)
// K0: pre-split offset-conv weights to bf16 hi/lo.
// K1: offset conv via bf16-split mma.sync; 512 threads / 16 warps (latency
//     hiding); direct-register epilogue; cp.async B fill overlap.
//     Scratch [b][pxblk][r][f][gs][px8].
// K2: softmax + bilinear + grouped main conv, thread per (pixel, group).

__device__ float g_off3[(size_t)8 * 512 * 144 * 96];      // 226 MB scratch
__device__ __nv_bfloat16 g_wsplit[1728 * 288];            // hi at k, lo at 144+k

// ---- smem geometry (bf16 elements, stride 296 = 288 data + 8 pad) ----
#define SASTRIDE 296
#define SA_BYTES (128 * SASTRIDE * 2)      // 75776
#define SB_BYTES (144 * SASTRIDE * 2)      // 85248
#define SM_TOT   (SA_BYTES + SB_BYTES)     // 161024

__device__ __forceinline__ uint32_t smem_u32(const void* p) {
    uint32_t a;
    asm("{ .reg .u64 t; cvta.to.shared.u64 t, %1; cvt.u32.u64 %0, t; }" : "=r"(a) : "l"(p));
    return a;
}
__device__ __forceinline__ void ldmA(uint32_t* r, uint32_t addr) {
    asm volatile("ldmatrix.sync.aligned.m8n8.x4.shared.b16 {%0,%1,%2,%3}, [%4];"
                 : "=r"(r[0]), "=r"(r[1]), "=r"(r[2]), "=r"(r[3]) : "r"(addr));
}
__device__ __forceinline__ void ldmB4(uint32_t* r, uint32_t addr) {
    asm volatile("ldmatrix.sync.aligned.m8n8.x4.shared.b16 {%0,%1,%2,%3}, [%4];"
                 : "=r"(r[0]), "=r"(r[1]), "=r"(r[2]), "=r"(r[3]) : "r"(addr));
}
__device__ __forceinline__ void ldmB2(uint32_t* r, uint32_t addr) {
    asm volatile("ldmatrix.sync.aligned.m8n8.x2.shared.b16 {%0,%1}, [%2];"
                 : "=r"(r[0]), "=r"(r[1]) : "r"(addr));
}
__device__ __forceinline__ void mma16816(float* d, const uint32_t* a, const uint32_t* b) {
    asm volatile("mma.sync.aligned.m16n8k16.row.col.f32.bf16.bf16.f32 "
                 "{%0,%1,%2,%3}, {%4,%5,%6,%7}, {%8,%9}, {%0,%1,%2,%3};"
                 : "+f"(d[0]), "+f"(d[1]), "+f"(d[2]), "+f"(d[3])
                 : "r"(a[0]), "r"(a[1]), "r"(a[2]), "r"(a[3]), "r"(b[0]), "r"(b[1]));
}
__device__ __forceinline__ void split1(float v, __nv_bfloat16& hi, __nv_bfloat16& lo) {
    hi = __float2bfloat16_rn(v);
    lo = __float2bfloat16_rn(v - __bfloat162float(hi));
}
__device__ __forceinline__ void cp_async16(uint32_t dst, const void* src) {
    asm volatile("cp.async.cg.shared.global [%0], [%1], 16;" :: "r"(dst), "l"(src));
}
__device__ __forceinline__ void cp_commit() { asm volatile("cp.async.commit_group;"); }
__device__ __forceinline__ void cp_wait0()  { asm volatile("cp.async.wait_group 0;" ::: "memory"); }

// ---------------------------------------------------------------------------
// K0: split weights once.
// ---------------------------------------------------------------------------
__global__ __launch_bounds__(256) void split_weights(const float* __restrict__ w_off) {
    int i = blockIdx.x * 256 + threadIdx.x;
    if (i >= 1728 * 144) return;
    int oc = i / 144, k = i % 144;
    __nv_bfloat16 hi, lo;
    split1(w_off[i], hi, lo);
    g_wsplit[oc * 288 + k] = hi;
    g_wsplit[oc * 288 + 144 + k] = lo;
}

// ---------------------------------------------------------------------------
// K1: grid (32 pxt, 4 g, 8 b), block 512 (16 warps, warp tile 16x72).
// ---------------------------------------------------------------------------
__global__ void __launch_bounds__(512) off_conv_mma(
    const float* __restrict__ in, const float* __restrict__ b_off)
{
    extern __shared__ char smem[];
    __shared__ int tabl[144];                 // (cg<<16)|(ky<<8)|kx
    __nv_bfloat16* sA = (__nv_bfloat16*)smem;
    __nv_bfloat16* sB = (__nv_bfloat16*)(smem + SA_BYTES);
    const uint32_t sAu = smem_u32(sA), sBu = smem_u32(sB);

    const int tid = threadIdx.x, wid = tid >> 5, lane = tid & 31;
    const int pxt = blockIdx.x, g = blockIdx.y, b = blockIdx.z;
    const int h0 = pxt * 2;

    if (tid < 144) {
        int cg = tid / 9, t = tid % 9;
        tabl[tid] = (cg << 16) | ((t / 3) << 8) | (t % 3);
    }

    // ---- issue B fill for sub=0 via cp.async ----
    {
        const int oc0 = g * 432;
        for (int i = tid; i < 144 * 36; i += 512) {
            int n = i / 36, q = i % 36;
            cp_async16(sBu + n * (SASTRIDE * 2) + q * 16,
                       (const char*)(g_wsplit + (size_t)(oc0 + n) * 288) + q * 16);
        }
        cp_commit();
    }
    __syncthreads();   // table visible

    // ---- A: im2col X[128 px][144 k] -> hi at k, lo at 144+k ----
    {
        const float* inb = in + ((size_t)(b * 64 + g * 16)) * 4096;
        const int m = tid >> 2;
        const int k0 = (tid & 3) * 36;
        const int h = h0 + (m >> 6), w = m & 63;
        __nv_bfloat16* rowp = sA + m * SASTRIDE;
#pragma unroll 6
        for (int j = 0; j < 36; ++j) {
            int k = k0 + j;
            int e = tabl[k];
            int cg = e >> 16, ky = (e >> 8) & 255, kx = e & 255;
            int ih = h - 1 + ky, iw = w - 1 + kx;
            float v = ((unsigned)ih < 64u && (unsigned)iw < 64u)
                      ? __ldg(inb + cg * 4096 + ih * 64 + iw) : 0.f;
            __nv_bfloat16 hi, lo; split1(v, hi, lo);
            rowp[k] = hi;
            rowp[144 + k] = lo;
        }
    }
    cp_wait0();
    __syncthreads();

    // warp tiles: 8 along M (16 rows), 2 along N (72 cols)
    const int wm = wid & 7, wn = wid >> 3;
    const int m_base = wm * 16, n_base = wn * 72;
    const int aRow = lane & 15, aColSel = (lane >> 4) << 3;
    const int bNlane = ((lane >> 4) << 3) + (lane & 7);
    const int bKlane = ((lane >> 3) & 1) << 3;

    for (int sub = 0; sub < 3; ++sub) {
        const int oc0 = g * 432 + sub * 144;

        float acc[9][4];
#pragma unroll
        for (int j = 0; j < 9; ++j)
#pragma unroll
            for (int q = 0; q < 4; ++q) acc[j][q] = 0.f;

#pragma unroll
        for (int term = 0; term < 3; ++term) {
            const int kAoff = (term == 2) ? 144 : 0;
            const int kBoff = (term == 1) ? 144 : 0;
#pragma unroll 3
            for (int j = 0; j < 9; ++j) {
                const int kA = kAoff + j * 16, kB = kBoff + j * 16;
                uint32_t afr[4];
                ldmA(afr, sAu + ((m_base + aRow) * SASTRIDE + kA + aColSel) * 2);
                uint32_t bfr[9][2];
#pragma unroll
                for (int pr = 0; pr < 4; ++pr) {
                    uint32_t tmp[4];
                    uint32_t addr = sBu + ((n_base + pr * 16 + bNlane) * SASTRIDE + kB + bKlane) * 2;
                    ldmB4(tmp, addr);
                    bfr[pr * 2][0] = tmp[0]; bfr[pr * 2][1] = tmp[1];
                    bfr[pr * 2 + 1][0] = tmp[2]; bfr[pr * 2 + 1][1] = tmp[3];
                }
                {
                    uint32_t addr = sBu + ((n_base + 64 + (lane & 7)) * SASTRIDE + kB + bKlane) * 2;
                    ldmB2(bfr[8], addr);
                }
#pragma unroll
                for (int nf = 0; nf < 9; ++nf)
                    mma16816(acc[nf], afr, bfr[nf]);
            }
        }
        __syncthreads();   // all warps done reading sB

        // ---- overlap: issue next sub's B fill while storing epilogue ----
        if (sub < 2) {
            const int oc1 = oc0 + 144;
            for (int i = tid; i < 144 * 36; i += 512) {
                int n = i / 36, q = i % 36;
                cp_async16(sBu + n * (SASTRIDE * 2) + q * 16,
                           (const char*)(g_wsplit + (size_t)(oc1 + n) * 288) + q * 16);
            }
            cp_commit();
        }

        // ---- direct-register epilogue: scratch [b][pxblk][r][f][gs][px8] ----
        {
            const int fg = 3 * g + sub;
            const int f = fg >> 2, gs = fg & 3;
            float* base = g_off3 + ((size_t)(b * 512 + pxt * 16)) * 13824 + f * 32 + gs * 8;
            const int r0 = n_base + ((lane & 3) << 1);
            const int pxa = m_base + (lane >> 2);
            const int pb = pxa + 8;
#pragma unroll
            for (int nf = 0; nf < 9; ++nf) {
                const int r = r0 + nf * 8;
                float2 bv = *(const float2*)(b_off + oc0 + r);
                float* pr_ = base + (size_t)r * 96;
                float* p0 = pr_ + (pxa >> 3) * 13824 + (pxa & 7);
                p0[0]  = acc[nf][0] + bv.x;
                p0[96] = acc[nf][1] + bv.y;
                float* p1 = pr_ + (pb >> 3) * 13824 + (pb & 7);
                p1[0]  = acc[nf][2] + bv.x;
                p1[96] = acc[nf][3] + bv.y;
            }
        }

        cp_wait0();
        __syncthreads();   // fresh sB ready
    }
}

// ---------------------------------------------------------------------------
// K2: thread per (pixel, group). Offset reads coalesced + streaming.
// ---------------------------------------------------------------------------
__global__ __launch_bounds__(256, 3) void deform_main_k2(
    const float* __restrict__ in, const float* __restrict__ wmain,
    const float* __restrict__ bias, float* __restrict__ out)
{
    __shared__ float sW[4 * 2308];   // [g] stride 2308 x [r][16 oc]
    for (int i = threadIdx.x; i < 64 * 144; i += 256) {
        int o = i / 144, r = i % 144;
        sW[(o >> 4) * 2308 + r * 16 + (o & 15)] = wmain[i];
    }
    __syncthreads();

    const int t = blockIdx.x * 256 + threadIdx.x;
    const int g = t & 3, p = t >> 2;
    const int b = p >> 12, h = (p >> 6) & 63, w = p & 63;

    const float* offb = g_off3 + (size_t)(p >> 3) * 13824 + g * 8 + (p & 7);
    const float* cinb = in + ((size_t)(b * 64 + g * 16)) * 4096;

    float acc[16];
#pragma unroll
    for (int o = 0; o < 16; ++o) acc[o] = 0.f;

#pragma unroll 2
    for (int cg = 0; cg < 16; ++cg) {
#pragma unroll
        for (int k = 0; k < 9; ++k) {
            const int r = cg * 9 + k;
            float dy = __ldcs(offb + r * 96);
            float dx = __ldcs(offb + r * 96 + 32);
            float lg = __ldcs(offb + r * 96 + 64);

            float m = lg;
            m = fmaxf(m, __shfl_xor_sync(0xFFFFFFFFu, m, 1));
            m = fmaxf(m, __shfl_xor_sync(0xFFFFFFFFu, m, 2));
            float e = __expf(lg - m);
            float s = e;
            s += __shfl_xor_sync(0xFFFFFFFFu, s, 1);
            s += __shfl_xor_sync(0xFFFFFFFFu, s, 2);
            float mask = e * __fdividef(1.f, s);

            float py = (float)(h + k / 3) + dy;
            float px = (float)(w + k % 3) + dx;
            float y0 = floorf(py), x0 = floorf(px);
            float wy = py - y0, wx = px - x0;
            int iy = (int)y0 - 1, ix = (int)x0 - 1;
            const float* cin = cinb + cg * 4096;
            bool yv0 = (unsigned)iy < 64u, yv1 = (unsigned)(iy + 1) < 64u;
            bool xv0 = (unsigned)ix < 64u, xv1 = (unsigned)(ix + 1) < 64u;
            float v00 = (yv0 && xv0) ? __ldg(cin + iy * 64 + ix) : 0.f;
            float v01 = (yv0 && xv1) ? __ldg(cin + iy * 64 + ix + 1) : 0.f;
            float v10 = (yv1 && xv0) ? __ldg(cin + (iy + 1) * 64 + ix) : 0.f;
            float v11 = (yv1 && xv1) ? __ldg(cin + (iy + 1) * 64 + ix + 1) : 0.f;
            float val = ((1.f - wy) * (1.f - wx) * v00 + (1.f - wy) * wx * v01 +
                         wy * (1.f - wx) * v10 + wy * wx * v11) * mask;

            const float4* wr = (const float4*)&sW[g * 2308 + r * 16];
            float4 w0 = wr[0], w1 = wr[1], w2 = wr[2], w3 = wr[3];
            acc[0]  = fmaf(w0.x, val, acc[0]);  acc[1]  = fmaf(w0.y, val, acc[1]);
            acc[2]  = fmaf(w0.z, val, acc[2]);  acc[3]  = fmaf(w0.w, val, acc[3]);
            acc[4]  = fmaf(w1.x, val, acc[4]);  acc[5]  = fmaf(w1.y, val, acc[5]);
            acc[6]  = fmaf(w1.z, val, acc[6]);  acc[7]  = fmaf(w1.w, val, acc[7]);
            acc[8]  = fmaf(w2.x, val, acc[8]);  acc[9]  = fmaf(w2.y, val, acc[9]);
            acc[10] = fmaf(w2.z, val, acc[10]); acc[11] = fmaf(w2.w, val, acc[11]);
            acc[12] = fmaf(w3.x, val, acc[12]); acc[13] = fmaf(w3.y, val, acc[13]);
            acc[14] = fmaf(w3.z, val, acc[14]); acc[15] = fmaf(w3.w, val, acc[15]);
        }
    }

    const int hw = p & 4095;
#pragma unroll
    for (int ol = 0; ol < 16; ++ol)
        out[((size_t)(b * 64 + g * 16 + ol)) * 4096 + hw] = acc[ol] + __ldg(bias + g * 16 + ol);
}

// ---------------------------------------------------------------------------
extern "C" void kernel_launch(void* const* d_in, const int* in_sizes, int n_in,
                              void* d_out, int out_size) {
    const float* inps   = (const float*)d_in[0];
    const float* weight = (const float*)d_in[1];
    const float* bias   = (const float*)d_in[2];
    const float* w_off  = (const float*)d_in[3];
    const float* b_off  = (const float*)d_in[4];
    float* out = (float*)d_out;

    cudaFuncSetAttribute(off_conv_mma, cudaFuncAttributeMaxDynamicSharedMemorySize, SM_TOT);
    split_weights<<<(1728 * 144 + 255) / 256, 256>>>(w_off);
    off_conv_mma<<<dim3(32, 4, 8), 512, SM_TOT>>>(inps, b_off);
    deform_main_k2<<<512, 256>>>(inps, weight, bias, out);
}

// round 11
// speedup vs baseline: 4.5096x; 1.3959x over previous
#include <cuda_runtime.h>
#include <cuda_fp16.h>
#include <cstdint>

// DeformConv2d B=8 C=64 H=W=64 G=4 3x3 pad1 (sm_100 base, mma.sync path)
// K0: convert offset-conv weights to fp16.
// K1: offset conv via single-pass fp16 mma.sync (3x fewer HMMA than the
//     bf16-split version); 512 threads, 2 CTAs/SM; direct-register epilogue;
//     cp.async B fill overlap. Scratch [b][pxblk][r][f][gs][px8] (fp32).
// K2: softmax + bilinear + grouped main conv, thread per (pixel, group).

__device__ float g_off3[(size_t)8 * 512 * 144 * 96];   // 226 MB scratch
__device__ __half g_whalf[1728 * 144];                 // fp16 weights

// ---- smem geometry (fp16 elements, stride 152 = 144 data + 8 pad) ----
#define SASTRIDE 152
#define SA_BYTES (128 * SASTRIDE * 2)      // 38912
#define SB_BYTES (144 * SASTRIDE * 2)      // 43776
#define SM_TOT   (SA_BYTES + SB_BYTES)     // 82688  -> 2 CTAs/SM

__device__ __forceinline__ uint32_t smem_u32(const void* p) {
    uint32_t a;
    asm("{ .reg .u64 t; cvta.to.shared.u64 t, %1; cvt.u32.u64 %0, t; }" : "=r"(a) : "l"(p));
    return a;
}
__device__ __forceinline__ void ldmA(uint32_t* r, uint32_t addr) {
    asm volatile("ldmatrix.sync.aligned.m8n8.x4.shared.b16 {%0,%1,%2,%3}, [%4];"
                 : "=r"(r[0]), "=r"(r[1]), "=r"(r[2]), "=r"(r[3]) : "r"(addr));
}
__device__ __forceinline__ void ldmB4(uint32_t* r, uint32_t addr) {
    asm volatile("ldmatrix.sync.aligned.m8n8.x4.shared.b16 {%0,%1,%2,%3}, [%4];"
                 : "=r"(r[0]), "=r"(r[1]), "=r"(r[2]), "=r"(r[3]) : "r"(addr));
}
__device__ __forceinline__ void ldmB2(uint32_t* r, uint32_t addr) {
    asm volatile("ldmatrix.sync.aligned.m8n8.x2.shared.b16 {%0,%1}, [%2];"
                 : "=r"(r[0]), "=r"(r[1]) : "r"(addr));
}
__device__ __forceinline__ void mma16816(float* d, const uint32_t* a, const uint32_t* b) {
    asm volatile("mma.sync.aligned.m16n8k16.row.col.f32.f16.f16.f32 "
                 "{%0,%1,%2,%3}, {%4,%5,%6,%7}, {%8,%9}, {%0,%1,%2,%3};"
                 : "+f"(d[0]), "+f"(d[1]), "+f"(d[2]), "+f"(d[3])
                 : "r"(a[0]), "r"(a[1]), "r"(a[2]), "r"(a[3]), "r"(b[0]), "r"(b[1]));
}
__device__ __forceinline__ void cp_async16(uint32_t dst, const void* src) {
    asm volatile("cp.async.cg.shared.global [%0], [%1], 16;" :: "r"(dst), "l"(src));
}
__device__ __forceinline__ void cp_commit() { asm volatile("cp.async.commit_group;"); }
__device__ __forceinline__ void cp_wait0()  { asm volatile("cp.async.wait_group 0;" ::: "memory"); }

// ---------------------------------------------------------------------------
// K0: convert weights to fp16 once.
// ---------------------------------------------------------------------------
__global__ __launch_bounds__(256) void conv_weights(const float* __restrict__ w_off) {
    int i = blockIdx.x * 256 + threadIdx.x;
    if (i < 1728 * 144) g_whalf[i] = __float2half_rn(w_off[i]);
}

// ---------------------------------------------------------------------------
// K1: grid (32 pxt, 4 g, 8 b), block 512 (16 warps, warp tile 16x72), 2 CTA/SM.
// ---------------------------------------------------------------------------
__global__ void __launch_bounds__(512, 2) off_conv_mma(
    const float* __restrict__ in, const float* __restrict__ b_off)
{
    extern __shared__ char smem[];
    __shared__ int tabl[144];                 // (cg<<16)|(ky<<8)|kx
    __half* sA = (__half*)smem;
    __half* sB = (__half*)(smem + SA_BYTES);
    const uint32_t sAu = smem_u32(sA), sBu = smem_u32(sB);

    const int tid = threadIdx.x, wid = tid >> 5, lane = tid & 31;
    const int pxt = blockIdx.x, g = blockIdx.y, b = blockIdx.z;
    const int h0 = pxt * 2;

    if (tid < 144) {
        int cg = tid / 9, t = tid % 9;
        tabl[tid] = (cg << 16) | ((t / 3) << 8) | (t % 3);
    }

    // ---- issue B fill for sub=0 via cp.async (144 rows x 288 B) ----
    {
        const int oc0 = g * 432;
        for (int i = tid; i < 144 * 18; i += 512) {
            int n = i / 18, q = i % 18;
            cp_async16(sBu + n * (SASTRIDE * 2) + q * 16,
                       (const char*)(g_whalf + (size_t)(oc0 + n) * 144) + q * 16);
        }
        cp_commit();
    }
    __syncthreads();   // table visible

    // ---- A: im2col X[128 px][144 k] fp16 ----
    {
        const float* inb = in + ((size_t)(b * 64 + g * 16)) * 4096;
        const int m = tid >> 2;
        const int k0 = (tid & 3) * 36;
        const int h = h0 + (m >> 6), w = m & 63;
        __half* rowp = sA + m * SASTRIDE;
#pragma unroll 6
        for (int j = 0; j < 36; ++j) {
            int k = k0 + j;
            int e = tabl[k];
            int cg = e >> 16, ky = (e >> 8) & 255, kx = e & 255;
            int ih = h - 1 + ky, iw = w - 1 + kx;
            float v = ((unsigned)ih < 64u && (unsigned)iw < 64u)
                      ? __ldg(inb + cg * 4096 + ih * 64 + iw) : 0.f;
            rowp[k] = __float2half_rn(v);
        }
    }
    cp_wait0();
    __syncthreads();

    // warp tiles: 8 along M (16 rows), 2 along N (72 cols)
    const int wm = wid & 7, wn = wid >> 3;
    const int m_base = wm * 16, n_base = wn * 72;
    const int aRow = lane & 15, aColSel = (lane >> 4) << 3;
    const int bNlane = ((lane >> 4) << 3) + (lane & 7);
    const int bKlane = ((lane >> 3) & 1) << 3;

    for (int sub = 0; sub < 3; ++sub) {
        const int oc0 = g * 432 + sub * 144;

        float acc[9][4];
#pragma unroll
        for (int j = 0; j < 9; ++j)
#pragma unroll
            for (int q = 0; q < 4; ++q) acc[j][q] = 0.f;

#pragma unroll 3
        for (int j = 0; j < 9; ++j) {
            const int kA = j * 16;
            uint32_t afr[4];
            ldmA(afr, sAu + ((m_base + aRow) * SASTRIDE + kA + aColSel) * 2);
            uint32_t bfr[9][2];
#pragma unroll
            for (int pr = 0; pr < 4; ++pr) {
                uint32_t tmp[4];
                uint32_t addr = sBu + ((n_base + pr * 16 + bNlane) * SASTRIDE + kA + bKlane) * 2;
                ldmB4(tmp, addr);
                bfr[pr * 2][0] = tmp[0]; bfr[pr * 2][1] = tmp[1];
                bfr[pr * 2 + 1][0] = tmp[2]; bfr[pr * 2 + 1][1] = tmp[3];
            }
            {
                uint32_t addr = sBu + ((n_base + 64 + (lane & 7)) * SASTRIDE + kA + bKlane) * 2;
                ldmB2(bfr[8], addr);
            }
#pragma unroll
            for (int nf = 0; nf < 9; ++nf)
                mma16816(acc[nf], afr, bfr[nf]);
        }
        __syncthreads();   // all warps done reading sB

        // ---- overlap: issue next sub's B fill while storing epilogue ----
        if (sub < 2) {
            const int oc1 = oc0 + 144;
            for (int i = tid; i < 144 * 18; i += 512) {
                int n = i / 18, q = i % 18;
                cp_async16(sBu + n * (SASTRIDE * 2) + q * 16,
                           (const char*)(g_whalf + (size_t)(oc1 + n) * 144) + q * 16);
            }
            cp_commit();
        }

        // ---- direct-register epilogue: scratch [b][pxblk][r][f][gs][px8] ----
        {
            const int fg = 3 * g + sub;
            const int f = fg >> 2, gs = fg & 3;
            float* base = g_off3 + ((size_t)(b * 512 + pxt * 16)) * 13824 + f * 32 + gs * 8;
            const int r0 = n_base + ((lane & 3) << 1);
            const int pxa = m_base + (lane >> 2);
            const int pb = pxa + 8;
#pragma unroll
            for (int nf = 0; nf < 9; ++nf) {
                const int r = r0 + nf * 8;
                float2 bv = *(const float2*)(b_off + oc0 + r);
                float* pr_ = base + (size_t)r * 96;
                float* p0 = pr_ + (pxa >> 3) * 13824 + (pxa & 7);
                p0[0]  = acc[nf][0] + bv.x;
                p0[96] = acc[nf][1] + bv.y;
                float* p1 = pr_ + (pb >> 3) * 13824 + (pb & 7);
                p1[0]  = acc[nf][2] + bv.x;
                p1[96] = acc[nf][3] + bv.y;
            }
        }

        cp_wait0();
        __syncthreads();   // fresh sB ready
    }
}

// ---------------------------------------------------------------------------
// K2: thread per (pixel, group). Offset reads coalesced + streaming.
// ---------------------------------------------------------------------------
__global__ __launch_bounds__(256, 3) void deform_main_k2(
    const float* __restrict__ in, const float* __restrict__ wmain,
    const float* __restrict__ bias, float* __restrict__ out)
{
    __shared__ float sW[4 * 2308];   // [g] stride 2308 x [r][16 oc]
    for (int i = threadIdx.x; i < 64 * 144; i += 256) {
        int o = i / 144, r = i % 144;
        sW[(o >> 4) * 2308 + r * 16 + (o & 15)] = wmain[i];
    }
    __syncthreads();

    const int t = blockIdx.x * 256 + threadIdx.x;
    const int g = t & 3, p = t >> 2;
    const int b = p >> 12, h = (p >> 6) & 63, w = p & 63;

    const float* offb = g_off3 + (size_t)(p >> 3) * 13824 + g * 8 + (p & 7);
    const float* cinb = in + ((size_t)(b * 64 + g * 16)) * 4096;

    float acc[16];
#pragma unroll
    for (int o = 0; o < 16; ++o) acc[o] = 0.f;

#pragma unroll 2
    for (int cg = 0; cg < 16; ++cg) {
#pragma unroll
        for (int k = 0; k < 9; ++k) {
            const int r = cg * 9 + k;
            float dy = __ldcs(offb + r * 96);
            float dx = __ldcs(offb + r * 96 + 32);
            float lg = __ldcs(offb + r * 96 + 64);

            float m = lg;
            m = fmaxf(m, __shfl_xor_sync(0xFFFFFFFFu, m, 1));
            m = fmaxf(m, __shfl_xor_sync(0xFFFFFFFFu, m, 2));
            float e = __expf(lg - m);
            float s = e;
            s += __shfl_xor_sync(0xFFFFFFFFu, s, 1);
            s += __shfl_xor_sync(0xFFFFFFFFu, s, 2);
            float mask = e * __fdividef(1.f, s);

            float py = (float)(h + k / 3) + dy;
            float px = (float)(w + k % 3) + dx;
            float y0 = floorf(py), x0 = floorf(px);
            float wy = py - y0, wx = px - x0;
            int iy = (int)y0 - 1, ix = (int)x0 - 1;
            const float* cin = cinb + cg * 4096;
            bool yv0 = (unsigned)iy < 64u, yv1 = (unsigned)(iy + 1) < 64u;
            bool xv0 = (unsigned)ix < 64u, xv1 = (unsigned)(ix + 1) < 64u;
            float v00 = (yv0 && xv0) ? __ldg(cin + iy * 64 + ix) : 0.f;
            float v01 = (yv0 && xv1) ? __ldg(cin + iy * 64 + ix + 1) : 0.f;
            float v10 = (yv1 && xv0) ? __ldg(cin + (iy + 1) * 64 + ix) : 0.f;
            float v11 = (yv1 && xv1) ? __ldg(cin + (iy + 1) * 64 + ix + 1) : 0.f;
            float val = ((1.f - wy) * (1.f - wx) * v00 + (1.f - wy) * wx * v01 +
                         wy * (1.f - wx) * v10 + wy * wx * v11) * mask;

            const float4* wr = (const float4*)&sW[g * 2308 + r * 16];
            float4 w0 = wr[0], w1 = wr[1], w2 = wr[2], w3 = wr[3];
            acc[0]  = fmaf(w0.x, val, acc[0]);  acc[1]  = fmaf(w0.y, val, acc[1]);
            acc[2]  = fmaf(w0.z, val, acc[2]);  acc[3]  = fmaf(w0.w, val, acc[3]);
            acc[4]  = fmaf(w1.x, val, acc[4]);  acc[5]  = fmaf(w1.y, val, acc[5]);
            acc[6]  = fmaf(w1.z, val, acc[6]);  acc[7]  = fmaf(w1.w, val, acc[7]);
            acc[8]  = fmaf(w2.x, val, acc[8]);  acc[9]  = fmaf(w2.y, val, acc[9]);
            acc[10] = fmaf(w2.z, val, acc[10]); acc[11] = fmaf(w2.w, val, acc[11]);
            acc[12] = fmaf(w3.x, val, acc[12]); acc[13] = fmaf(w3.y, val, acc[13]);
            acc[14] = fmaf(w3.z, val, acc[14]); acc[15] = fmaf(w3.w, val, acc[15]);
        }
    }

    const int hw = p & 4095;
#pragma unroll
    for (int ol = 0; ol < 16; ++ol)
        out[((size_t)(b * 64 + g * 16 + ol)) * 4096 + hw] = acc[ol] + __ldg(bias + g * 16 + ol);
}

// ---------------------------------------------------------------------------
extern "C" void kernel_launch(void* const* d_in, const int* in_sizes, int n_in,
                              void* d_out, int out_size) {
    const float* inps   = (const float*)d_in[0];
    const float* weight = (const float*)d_in[1];
    const float* bias   = (const float*)d_in[2];
    const float* w_off  = (const float*)d_in[3];
    const float* b_off  = (const float*)d_in[4];
    float* out = (float*)d_out;

    cudaFuncSetAttribute(off_conv_mma, cudaFuncAttributeMaxDynamicSharedMemorySize, SM_TOT);
    conv_weights<<<(1728 * 144 + 255) / 256, 256>>>(w_off);
    off_conv_mma<<<dim3(32, 4, 8), 512, SM_TOT>>>(inps, b_off);
    deform_main_k2<<<512, 256>>>(inps, weight, bias, out);
}